// round 1
// baseline (speedup 1.0000x reference)
#include <cuda_runtime.h>
#include <math.h>

// Problem constants
#define BB   64
#define TT   256
#define DD   1024
#define HH   1024
#define G4   4096      // 4*H
#define MROWS (BB*TT)  // 16384

// Scratch (static device allocations — allowed; no cudaMalloc anywhere)
__device__ float g_xz[2][MROWS][G4];       // input projections, fwd/bwd (536 MB)
__device__ float g_h[2][2][BB][HH];        // h state, [buffer][dir][b][j]
__device__ float g_c[2][BB][HH];           // c state, [dir][b][j]

// ---------------------------------------------------------------------------
// Zero h (both buffers) and c state. 2*2*64*1024 + 2*64*1024 = 393216 floats.
// ---------------------------------------------------------------------------
__global__ void init_state_kernel() {
    int idx = blockIdx.x * blockDim.x + threadIdx.x;
    float* h = &g_h[0][0][0][0];
    float* c = &g_c[0][0][0];
    const int NH = 2 * 2 * BB * HH;
    const int NC = 2 * BB * HH;
    if (idx < NH) h[idx] = 0.0f;
    if (idx < NC) c[idx] = 0.0f;
}

// ---------------------------------------------------------------------------
// Input projection: g_xz[dir][b*T+t][g] = sum_d x[b,t,d] * W[d,g] + bias[g]
// M=16384, N=4096 per dir, K=1024. Tiles: BM=128, BN=128, BK=8, 256 thr, 8x8/thr.
// grid = (64, 128): blockIdx.x = dir*32 + ntile, blockIdx.y = mtile
// ---------------------------------------------------------------------------
__global__ __launch_bounds__(256)
void input_gemm_kernel(const float* __restrict__ x,
                       const float* __restrict__ Wf, const float* __restrict__ bf,
                       const float* __restrict__ Wb, const float* __restrict__ bb)
{
    const int dir = blockIdx.x >> 5;
    const int nt  = blockIdx.x & 31;
    const int m0  = blockIdx.y * 128;
    const int n0  = nt * 128;
    const float* __restrict__ W    = dir ? Wb : Wf;
    const float* __restrict__ bias = dir ? bb : bf;

    __shared__ float As[8][128];
    __shared__ float Bs[8][128];

    const int tid = threadIdx.x;
    const int tm = tid >> 4;      // 0..15 -> rows tm*8..+7
    const int tn = tid & 15;      // 0..15 -> cols tn*8..+7

    // loader indices
    const int arow  = tid >> 1;          // 0..127
    const int acol4 = (tid & 1) * 4;     // 0 or 4
    const int brow  = tid >> 5;          // 0..7
    const int bcol  = (tid & 31) * 4;    // 0..124

    float acc[8][8] = {};

    const float* __restrict__ aptr = x + (size_t)(m0 + arow) * DD + acol4;
    const float* __restrict__ bptr = W + (size_t)brow * G4 + n0 + bcol;

    for (int k0 = 0; k0 < DD; k0 += 8) {
        float4 av = *(const float4*)(aptr + k0);
        float4 bv = *(const float4*)(bptr + (size_t)k0 * G4);
        As[acol4 + 0][arow] = av.x;
        As[acol4 + 1][arow] = av.y;
        As[acol4 + 2][arow] = av.z;
        As[acol4 + 3][arow] = av.w;
        *(float4*)&Bs[brow][bcol] = bv;
        __syncthreads();

        #pragma unroll
        for (int k = 0; k < 8; k++) {
            float ra[8], rbv[8];
            *(float4*)&ra[0]  = *(const float4*)&As[k][tm * 8];
            *(float4*)&ra[4]  = *(const float4*)&As[k][tm * 8 + 4];
            *(float4*)&rbv[0] = *(const float4*)&Bs[k][tn * 8];
            *(float4*)&rbv[4] = *(const float4*)&Bs[k][tn * 8 + 4];
            #pragma unroll
            for (int i = 0; i < 8; i++)
                #pragma unroll
                for (int j = 0; j < 8; j++)
                    acc[i][j] += ra[i] * rbv[j];
        }
        __syncthreads();
    }

    // epilogue: add bias, store float4
    float bload[8];
    *(float4*)&bload[0] = *(const float4*)&bias[n0 + tn * 8];
    *(float4*)&bload[4] = *(const float4*)&bias[n0 + tn * 8 + 4];
    #pragma unroll
    for (int i = 0; i < 8; i++) {
        const int row = m0 + tm * 8 + i;
        float* dst = &g_xz[dir][row][n0 + tn * 8];
        float4 v0 = make_float4(acc[i][0] + bload[0], acc[i][1] + bload[1],
                                acc[i][2] + bload[2], acc[i][3] + bload[3]);
        float4 v1 = make_float4(acc[i][4] + bload[4], acc[i][5] + bload[5],
                                acc[i][6] + bload[6], acc[i][7] + bload[7]);
        *(float4*)&dst[0] = v0;
        *(float4*)&dst[4] = v1;
    }
}

// ---------------------------------------------------------------------------
// One LSTM timestep, both directions.
// grid = (64, 2): blockIdx.x = j-tile (16 wide), blockIdx.y = dir.
// Block computes z[b][q*H + j0+jj] for b=0..63, q=0..3, jj=0..15 via
// z = xz[t] + h_prev @ U, then gates, c/h update, writes h to state+output.
// h double-buffered across steps (read s&1, write (s+1)&1) to avoid the
// cross-block read-after-write race on h within one step.
// ---------------------------------------------------------------------------
__device__ __forceinline__ float sigmoidf_(float v) {
    return 1.0f / (1.0f + __expf(-v));
}

__global__ __launch_bounds__(256)
void lstm_step_kernel(const float* __restrict__ Uf, const float* __restrict__ Ub,
                      float* __restrict__ out, int s)
{
    const int dir = blockIdx.y;
    const int j0  = blockIdx.x * 16;
    const float* __restrict__ U = dir ? Ub : Uf;
    const int t  = dir ? (TT - 1 - s) : s;
    const int rb = s & 1;
    const int wbuf = rb ^ 1;

    __shared__ float Hs[16][64];   // [k][b]
    __shared__ float Us[16][64];   // [k][jj*4 + gate]

    const int tid = threadIdx.x;
    const int tm = tid >> 4;       // 0..15 -> rows (b) tm*4..+3
    const int tn = tid & 15;       // j lane (jj)

    // loader indices
    const int hb  = tid >> 2;          // 0..63
    const int hk4 = (tid & 3) * 4;     // 0,4,8,12
    const int ukk = tid >> 4;          // 0..15
    const int ulane = tid & 15;

    float acc[4][4] = {};   // acc[r][gate]

    const float* __restrict__ hsrc = &g_h[rb][dir][hb][hk4];
    const float* __restrict__ ubase = U + (size_t)ukk * G4 + j0 + ulane;

    for (int k0 = 0; k0 < HH; k0 += 16) {
        float4 hv = *(const float4*)(hsrc + k0);
        const float* up = ubase + (size_t)k0 * G4;
        float4 uv = make_float4(up[0], up[HH], up[2 * HH], up[3 * HH]);

        Hs[hk4 + 0][hb] = hv.x;
        Hs[hk4 + 1][hb] = hv.y;
        Hs[hk4 + 2][hb] = hv.z;
        Hs[hk4 + 3][hb] = hv.w;
        *(float4*)&Us[ukk][ulane * 4] = uv;
        __syncthreads();

        #pragma unroll
        for (int k = 0; k < 16; k++) {
            float h4[4], u4[4];
            *(float4*)&h4[0] = *(const float4*)&Hs[k][tm * 4];
            *(float4*)&u4[0] = *(const float4*)&Us[k][tn * 4];
            #pragma unroll
            for (int r = 0; r < 4; r++)
                #pragma unroll
                for (int q = 0; q < 4; q++)
                    acc[r][q] += h4[r] * u4[q];
        }
        __syncthreads();
    }

    const int j = j0 + tn;
    #pragma unroll
    for (int r = 0; r < 4; r++) {
        const int b = tm * 4 + r;
        const int row = b * TT + t;
        const float* xz = &g_xz[dir][row][j];
        float zi = acc[r][0] + xz[0];
        float zf = acc[r][1] + xz[HH];
        float zg = acc[r][2] + xz[2 * HH];
        float zo = acc[r][3] + xz[3 * HH];

        float gi = sigmoidf_(zi);
        float gf = sigmoidf_(zf);
        float gg = tanhf(zg);
        float go = sigmoidf_(zo);

        float c = gf * g_c[dir][b][j] + gi * gg;
        g_c[dir][b][j] = c;
        float h = go * tanhf(c);
        g_h[wbuf][dir][b][j] = h;

        out[(size_t)b * (TT * 2 * HH) + (size_t)t * (2 * HH) + dir * HH + j] = h;
    }
}

// ---------------------------------------------------------------------------
// Launch: init state -> input GEMM -> 256 fused LSTM steps (both dirs each).
// All plain kernel launches on the capture stream; no sync, no allocation.
// ---------------------------------------------------------------------------
extern "C" void kernel_launch(void* const* d_in, const int* in_sizes, int n_in,
                              void* d_out, int out_size)
{
    const float* x  = (const float*)d_in[0];
    const float* Wf = (const float*)d_in[1];
    const float* Uf = (const float*)d_in[2];
    const float* bf = (const float*)d_in[3];
    const float* Wb = (const float*)d_in[4];
    const float* Ub = (const float*)d_in[5];
    const float* bb = (const float*)d_in[6];
    float* out = (float*)d_out;

    init_state_kernel<<<1536, 256>>>();

    dim3 ggrid(64, 128);
    input_gemm_kernel<<<ggrid, 256>>>(x, Wf, bf, Wb, bb);

    dim3 sgrid(64, 2);
    for (int s = 0; s < TT; s++) {
        lstm_step_kernel<<<sgrid, 256>>>(Uf, Ub, out, s);
    }
}

// round 6
// speedup vs baseline: 1.0924x; 1.0924x over previous
#include <cuda_runtime.h>
#include <math.h>

// Problem constants
#define BB   64
#define TT   256
#define DD   1024
#define HH   1024
#define G4   4096      // 4*H
#define MROWS (BB*TT)  // 16384

// Scratch (static device allocations — allowed; no cudaMalloc anywhere)
__device__ float g_xz[2][MROWS][G4];       // input projections, fwd/bwd (536 MB)
__device__ float g_h[2][2][BB][HH];        // h state, [buffer][dir][b][j]
__device__ float g_c[2][BB][HH];           // c state, [dir][b][j]

// ---------------------------------------------------------------------------
// Packed f32x2 helpers (Blackwell sm_103a): one FFMA2 = 2 fp32 MACs at the
// same fma-pipe issue rate as one FFMA -> 2x fp32 throughput.
// ---------------------------------------------------------------------------
typedef unsigned long long u64;

__device__ __forceinline__ u64 fma2_(u64 a, u64 b, u64 c) {
    u64 d;
    asm("fma.rn.f32x2 %0, %1, %2, %3;" : "=l"(d) : "l"(a), "l"(b), "l"(c));
    return d;
}
__device__ __forceinline__ u64 add2_(u64 a, u64 b) {
    u64 d;
    asm("add.rn.f32x2 %0, %1, %2;" : "=l"(d) : "l"(a), "l"(b));
    return d;
}
__device__ __forceinline__ u64 pack2_(float v) {   // (v, v)
    u64 d;
    asm("mov.b64 %0, {%1, %1};" : "=l"(d) : "r"(__float_as_uint(v)));
    return d;
}
__device__ __forceinline__ void unpack2_(u64 v, float& lo, float& hi) {
    asm("mov.b64 {%0, %1}, %2;" : "=f"(lo), "=f"(hi) : "l"(v));
}
__device__ __forceinline__ double ull_as_d(u64 v) {
    return __longlong_as_double((long long)v);
}

// ---------------------------------------------------------------------------
// Zero h (both buffers) and c state.
// ---------------------------------------------------------------------------
__global__ void init_state_kernel() {
    int idx = blockIdx.x * blockDim.x + threadIdx.x;
    float* h = &g_h[0][0][0][0];
    float* c = &g_c[0][0][0];
    const int NH = 2 * 2 * BB * HH;
    const int NC = 2 * BB * HH;
    if (idx < NH) h[idx] = 0.0f;
    if (idx < NC) c[idx] = 0.0f;
}

// ---------------------------------------------------------------------------
// Input projection: g_xz[dir][b*T+t][g] = sum_d x[b,t,d] * W[d,g] + bias[g]
// M=16384, N=4096/dir, K=1024. BM=128, BN=128, BK=8, 256 thr, 8x8 per thread.
// f32x2 packed FMA along the j dimension: acc2[i][p] holds cols (2p, 2p+1).
// Double-buffered SMEM, one barrier per chunk; streaming stores of g_xz.
// grid = (64, 128): blockIdx.x = dir*32 + ntile, blockIdx.y = mtile
// ---------------------------------------------------------------------------
__global__ __launch_bounds__(256)
void input_gemm_kernel(const float* __restrict__ x,
                       const float* __restrict__ Wf, const float* __restrict__ bf,
                       const float* __restrict__ Wb, const float* __restrict__ bb)
{
    const int dir = blockIdx.x >> 5;
    const int nt  = blockIdx.x & 31;
    const int m0  = blockIdx.y * 128;
    const int n0  = nt * 128;
    const float* __restrict__ W    = dir ? Wb : Wf;
    const float* __restrict__ bias = dir ? bb : bf;

    __shared__ float As[2][8][128];
    __shared__ float Bs[2][8][128];

    const int tid = threadIdx.x;
    const int tm = tid >> 4;      // 0..15 -> rows tm*8..+7
    const int tn = tid & 15;      // 0..15 -> cols tn*8..+7

    const int arow  = tid >> 1;          // 0..127
    const int acol4 = (tid & 1) * 4;     // 0 or 4
    const int brow  = tid >> 5;          // 0..7
    const int bcol  = (tid & 31) * 4;    // 0..124

    u64 acc2[8][4];
    #pragma unroll
    for (int i = 0; i < 8; i++)
        #pragma unroll
        for (int p = 0; p < 4; p++) acc2[i][p] = 0ull;   // (0.0f, 0.0f)

    const float* __restrict__ aptr = x + (size_t)(m0 + arow) * DD + acol4;
    const float* __restrict__ bptr = W + (size_t)brow * G4 + n0 + bcol;

    // prefetch chunk 0
    float4 av = *(const float4*)(aptr);
    float4 bv = *(const float4*)(bptr);

    const int NCHUNK = DD / 8;  // 128
    for (int c = 0; c < NCHUNK; c++) {
        const int buf = c & 1;
        As[buf][acol4 + 0][arow] = av.x;
        As[buf][acol4 + 1][arow] = av.y;
        As[buf][acol4 + 2][arow] = av.z;
        As[buf][acol4 + 3][arow] = av.w;
        *(float4*)&Bs[buf][brow][bcol] = bv;
        __syncthreads();

        if (c + 1 < NCHUNK) {
            const int k0 = (c + 1) * 8;
            av = *(const float4*)(aptr + k0);
            bv = *(const float4*)(bptr + (size_t)k0 * G4);
        }

        #pragma unroll
        for (int k = 0; k < 8; k++) {
            float4 a0 = *(const float4*)&As[buf][k][tm * 8];
            float4 a1 = *(const float4*)&As[buf][k][tm * 8 + 4];
            ulonglong2 b0 = *(const ulonglong2*)&Bs[buf][k][tn * 8];      // cols 0-3 as 2 pairs
            ulonglong2 b1 = *(const ulonglong2*)&Bs[buf][k][tn * 8 + 4];  // cols 4-7
            u64 bp0 = b0.x, bp1 = b0.y, bp2 = b1.x, bp3 = b1.y;
            float ra[8] = {a0.x, a0.y, a0.z, a0.w, a1.x, a1.y, a1.z, a1.w};
            #pragma unroll
            for (int i = 0; i < 8; i++) {
                u64 ad = pack2_(ra[i]);
                acc2[i][0] = fma2_(ad, bp0, acc2[i][0]);
                acc2[i][1] = fma2_(ad, bp1, acc2[i][1]);
                acc2[i][2] = fma2_(ad, bp2, acc2[i][2]);
                acc2[i][3] = fma2_(ad, bp3, acc2[i][3]);
            }
        }
        // single barrier per chunk: a thread reaches barrier B_c only after
        // finishing reads of buf_{c-1}; the next write to it is after B_c.
    }

    // epilogue: packed bias add, streaming 16B stores (keep W/U L2-resident)
    union { float4 f; ulonglong2 u; } bv0, bv1;
    bv0.f = *(const float4*)&bias[n0 + tn * 8];
    bv1.f = *(const float4*)&bias[n0 + tn * 8 + 4];
    u64 bias2[4] = {bv0.u.x, bv0.u.y, bv1.u.x, bv1.u.y};

    #pragma unroll
    for (int i = 0; i < 8; i++) {
        const int row = m0 + tm * 8 + i;
        float* dst = &g_xz[dir][row][n0 + tn * 8];
        double2 o0, o1;
        o0.x = ull_as_d(add2_(acc2[i][0], bias2[0]));
        o0.y = ull_as_d(add2_(acc2[i][1], bias2[1]));
        o1.x = ull_as_d(add2_(acc2[i][2], bias2[2]));
        o1.y = ull_as_d(add2_(acc2[i][3], bias2[3]));
        __stcs((double2*)&dst[0], o0);
        __stcs((double2*)&dst[4], o1);
    }
}

// ---------------------------------------------------------------------------
// One LSTM timestep, both directions. grid=(64,2), 256 threads.
// z[64 x 64cols] = xz[t] + h_prev @ U, fused gates + c/h update + output.
// f32x2 packed along batch pairs: acc2[r2][q] = rows (2*r2, 2*r2+1), gate q.
// h-pairs come free from an LDS.128 reinterpret; u is broadcast-packed (alu
// pipe, overlaps fma pipe). xz via __ldcs / out via __stcs so U stays in L2.
// ---------------------------------------------------------------------------
__device__ __forceinline__ float sigmoidf_(float v) {
    return 1.0f / (1.0f + __expf(-v));
}

#define HSPAD 68   // row pad (words); multiple of 4 keeps 16B alignment

__global__ __launch_bounds__(256)
void lstm_step_kernel(const float* __restrict__ Uf, const float* __restrict__ Ub,
                      float* __restrict__ out, int s)
{
    const int dir = blockIdx.y;
    const int j0  = blockIdx.x * 16;
    const float* __restrict__ U = dir ? Ub : Uf;
    const int t  = dir ? (TT - 1 - s) : s;
    const int rb = s & 1;
    const int wbuf = rb ^ 1;

    __shared__ float Hs[2][16][HSPAD];   // [buf][k][b]
    __shared__ float Us[2][16][HSPAD];   // [buf][k][jj*4 + gate]

    const int tid = threadIdx.x;
    const int tm = tid >> 4;       // 0..15 -> rows (b) tm*4..+3
    const int tn = tid & 15;       // j lane (jj)

    const int hb  = tid >> 2;          // 0..63
    const int hk4 = (tid & 3) * 4;     // 0,4,8,12
    const int ukk = tid >> 4;          // 0..15
    const int ulane = tid & 15;

    // prefetch xz for the epilogue (streaming: evict-first)
    const int j = j0 + tn;
    float xzv[4][4];
    #pragma unroll
    for (int r = 0; r < 4; r++) {
        const int b = tm * 4 + r;
        const float* xz = &g_xz[dir][(size_t)b * TT + t][j];
        xzv[r][0] = __ldcs(xz);
        xzv[r][1] = __ldcs(xz + HH);
        xzv[r][2] = __ldcs(xz + 2 * HH);
        xzv[r][3] = __ldcs(xz + 3 * HH);
    }

    u64 acc2[2][4];   // [row-pair][gate]
    #pragma unroll
    for (int r2 = 0; r2 < 2; r2++)
        #pragma unroll
        for (int q = 0; q < 4; q++) acc2[r2][q] = 0ull;

    const float* __restrict__ hsrc  = &g_h[rb][dir][hb][hk4];
    const float* __restrict__ ubase = U + (size_t)ukk * G4 + j0 + ulane;

    // prefetch chunk 0
    float4 rh = *(const float4*)(hsrc);
    float4 ru = make_float4(ubase[0], ubase[HH], ubase[2 * HH], ubase[3 * HH]);

    const int NCHUNK = HH / 16;  // 64
    for (int c = 0; c < NCHUNK; c++) {
        const int buf = c & 1;
        Hs[buf][hk4 + 0][hb] = rh.x;
        Hs[buf][hk4 + 1][hb] = rh.y;
        Hs[buf][hk4 + 2][hb] = rh.z;
        Hs[buf][hk4 + 3][hb] = rh.w;
        *(float4*)&Us[buf][ukk][ulane * 4] = ru;
        __syncthreads();

        if (c + 1 < NCHUNK) {
            const int k0 = (c + 1) * 16;
            rh = *(const float4*)(hsrc + k0);
            const float* up = ubase + (size_t)k0 * G4;
            ru = make_float4(up[0], up[HH], up[2 * HH], up[3 * HH]);
        }

        #pragma unroll
        for (int k = 0; k < 16; k++) {
            ulonglong2 hp = *(const ulonglong2*)&Hs[buf][k][tm * 4];  // (b0,b1),(b2,b3)
            float4 u4 = *(const float4*)&Us[buf][k][tn * 4];
            u64 ui = pack2_(u4.x);
            u64 uf = pack2_(u4.y);
            u64 ug = pack2_(u4.z);
            u64 uo = pack2_(u4.w);
            acc2[0][0] = fma2_(hp.x, ui, acc2[0][0]);
            acc2[0][1] = fma2_(hp.x, uf, acc2[0][1]);
            acc2[0][2] = fma2_(hp.x, ug, acc2[0][2]);
            acc2[0][3] = fma2_(hp.x, uo, acc2[0][3]);
            acc2[1][0] = fma2_(hp.y, ui, acc2[1][0]);
            acc2[1][1] = fma2_(hp.y, uf, acc2[1][1]);
            acc2[1][2] = fma2_(hp.y, ug, acc2[1][2]);
            acc2[1][3] = fma2_(hp.y, uo, acc2[1][3]);
        }
    }

    // unpack accumulators: acc2[r2][q] -> rows (2*r2, 2*r2+1)
    float accf[4][4];
    #pragma unroll
    for (int r2 = 0; r2 < 2; r2++)
        #pragma unroll
        for (int q = 0; q < 4; q++)
            unpack2_(acc2[r2][q], accf[2 * r2][q], accf[2 * r2 + 1][q]);

    #pragma unroll
    for (int r = 0; r < 4; r++) {
        const int b = tm * 4 + r;
        float zi = accf[r][0] + xzv[r][0];
        float zf = accf[r][1] + xzv[r][1];
        float zg = accf[r][2] + xzv[r][2];
        float zo = accf[r][3] + xzv[r][3];

        float gi = sigmoidf_(zi);
        float gf = sigmoidf_(zf);
        float gg = tanhf(zg);
        float go = sigmoidf_(zo);

        float c = gf * g_c[dir][b][j] + gi * gg;
        g_c[dir][b][j] = c;
        float h = go * tanhf(c);
        g_h[wbuf][dir][b][j] = h;

        // streaming store: output stream must not evict U from L2
        __stcs(&out[(size_t)b * (TT * 2 * HH) + (size_t)t * (2 * HH) + dir * HH + j], h);
    }
}

// ---------------------------------------------------------------------------
// Launch: init state -> input GEMM -> 256 fused LSTM steps (both dirs each).
// ---------------------------------------------------------------------------
extern "C" void kernel_launch(void* const* d_in, const int* in_sizes, int n_in,
                              void* d_out, int out_size)
{
    const float* x  = (const float*)d_in[0];
    const float* Wf = (const float*)d_in[1];
    const float* Uf = (const float*)d_in[2];
    const float* bf = (const float*)d_in[3];
    const float* Wb = (const float*)d_in[4];
    const float* Ub = (const float*)d_in[5];
    const float* bb = (const float*)d_in[6];
    float* out = (float*)d_out;

    init_state_kernel<<<1536, 256>>>();

    dim3 ggrid(64, 128);
    input_gemm_kernel<<<ggrid, 256>>>(x, Wf, bf, Wb, bb);

    dim3 sgrid(64, 2);
    for (int s = 0; s < TT; s++) {
        lstm_step_kernel<<<sgrid, 256>>>(Uf, Ub, out, s);
    }
}

// round 8
// speedup vs baseline: 1.3228x; 1.2110x over previous
#include <cuda_runtime.h>
#include <math.h>

// Problem constants
#define BB   64
#define TT   256
#define DD   1024
#define HH   1024
#define G4   4096      // 4*H
#define MROWS (BB*TT)  // 16384
#define NBLK 128u      // persistent grid size (must be <= SM count, all co-resident)

// Scratch (static device allocations — allowed; no cudaMalloc anywhere)
__device__ float g_xz[2][MROWS][G4];       // input projections, fwd/bwd (536 MB)
__device__ float g_h[2][2][BB][HH];        // h state, [buffer][dir][b][j]
__device__ unsigned g_bar;                 // grid barrier counter

// ---------------------------------------------------------------------------
// Packed f32x2 helpers: one FFMA2 = 2 fp32 MACs per fma-pipe issue.
// ---------------------------------------------------------------------------
typedef unsigned long long u64;

__device__ __forceinline__ u64 fma2_(u64 a, u64 b, u64 c) {
    u64 d;
    asm("fma.rn.f32x2 %0, %1, %2, %3;" : "=l"(d) : "l"(a), "l"(b), "l"(c));
    return d;
}
__device__ __forceinline__ u64 add2_(u64 a, u64 b) {
    u64 d;
    asm("add.rn.f32x2 %0, %1, %2;" : "=l"(d) : "l"(a), "l"(b));
    return d;
}
__device__ __forceinline__ u64 pack2_(float v) {   // (v, v)
    u64 d;
    asm("mov.b64 %0, {%1, %1};" : "=l"(d) : "r"(__float_as_uint(v)));
    return d;
}
__device__ __forceinline__ void unpack2_(u64 v, float& lo, float& hi) {
    asm("mov.b64 {%0, %1}, %2;" : "=f"(lo), "=f"(hi) : "l"(v));
}
__device__ __forceinline__ double ull_as_d(u64 v) {
    return __longlong_as_double((long long)v);
}

// ---------------------------------------------------------------------------
// Reset the grid-barrier counter (fresh on every graph replay).
// ---------------------------------------------------------------------------
__global__ void reset_kernel() { g_bar = 0u; }

// ---------------------------------------------------------------------------
// Grid-wide barrier for a fully co-resident grid.
// Release-arrive orders this block's prior (post-__syncthreads) stores;
// acquire-spin + __syncthreads propagates visibility to all block threads.
// Transitive happens-before: otherThread.st -> BAR -> t0 release-add ->
// observer t0 acquire-load -> BAR -> observer threads. (CG grid.sync pattern.)
// ---------------------------------------------------------------------------
__device__ __forceinline__ void grid_barrier(unsigned target) {
    __syncthreads();
    if (threadIdx.x == 0) {
        unsigned* p = &g_bar;
        asm volatile("red.release.gpu.global.add.u32 [%0], 1;" :: "l"(p) : "memory");
        unsigned v;
        for (;;) {
            asm volatile("ld.acquire.gpu.global.u32 %0, [%1];" : "=r"(v) : "l"(p) : "memory");
            if (v >= target) break;
            __nanosleep(64);
        }
    }
    __syncthreads();
}

// ---------------------------------------------------------------------------
// Input projection: g_xz[dir][b*T+t][g] = sum_d x[b,t,d] * W[d,g] + bias[g]
// (unchanged from R6 — FFMA2, double-buffered, single barrier, streaming out)
// grid = (64, 128): blockIdx.x = dir*32 + ntile, blockIdx.y = mtile
// ---------------------------------------------------------------------------
__global__ __launch_bounds__(256)
void input_gemm_kernel(const float* __restrict__ x,
                       const float* __restrict__ Wf, const float* __restrict__ bf,
                       const float* __restrict__ Wb, const float* __restrict__ bb)
{
    const int dir = blockIdx.x >> 5;
    const int nt  = blockIdx.x & 31;
    const int m0  = blockIdx.y * 128;
    const int n0  = nt * 128;
    const float* __restrict__ W    = dir ? Wb : Wf;
    const float* __restrict__ bias = dir ? bb : bf;

    __shared__ float As[2][8][128];
    __shared__ float Bs[2][8][128];

    const int tid = threadIdx.x;
    const int tm = tid >> 4;
    const int tn = tid & 15;

    const int arow  = tid >> 1;
    const int acol4 = (tid & 1) * 4;
    const int brow  = tid >> 5;
    const int bcol  = (tid & 31) * 4;

    u64 acc2[8][4];
    #pragma unroll
    for (int i = 0; i < 8; i++)
        #pragma unroll
        for (int p = 0; p < 4; p++) acc2[i][p] = 0ull;

    const float* __restrict__ aptr = x + (size_t)(m0 + arow) * DD + acol4;
    const float* __restrict__ bptr = W + (size_t)brow * G4 + n0 + bcol;

    float4 av = *(const float4*)(aptr);
    float4 bv = *(const float4*)(bptr);

    const int NCHUNK = DD / 8;  // 128
    for (int c = 0; c < NCHUNK; c++) {
        const int buf = c & 1;
        As[buf][acol4 + 0][arow] = av.x;
        As[buf][acol4 + 1][arow] = av.y;
        As[buf][acol4 + 2][arow] = av.z;
        As[buf][acol4 + 3][arow] = av.w;
        *(float4*)&Bs[buf][brow][bcol] = bv;
        __syncthreads();

        if (c + 1 < NCHUNK) {
            const int k0 = (c + 1) * 8;
            av = *(const float4*)(aptr + k0);
            bv = *(const float4*)(bptr + (size_t)k0 * G4);
        }

        #pragma unroll
        for (int k = 0; k < 8; k++) {
            float4 a0 = *(const float4*)&As[buf][k][tm * 8];
            float4 a1 = *(const float4*)&As[buf][k][tm * 8 + 4];
            ulonglong2 b0 = *(const ulonglong2*)&Bs[buf][k][tn * 8];
            ulonglong2 b1 = *(const ulonglong2*)&Bs[buf][k][tn * 8 + 4];
            u64 bp0 = b0.x, bp1 = b0.y, bp2 = b1.x, bp3 = b1.y;
            float ra[8] = {a0.x, a0.y, a0.z, a0.w, a1.x, a1.y, a1.z, a1.w};
            #pragma unroll
            for (int i = 0; i < 8; i++) {
                u64 ad = pack2_(ra[i]);
                acc2[i][0] = fma2_(ad, bp0, acc2[i][0]);
                acc2[i][1] = fma2_(ad, bp1, acc2[i][1]);
                acc2[i][2] = fma2_(ad, bp2, acc2[i][2]);
                acc2[i][3] = fma2_(ad, bp3, acc2[i][3]);
            }
        }
    }

    union { float4 f; ulonglong2 u; } bv0, bv1;
    bv0.f = *(const float4*)&bias[n0 + tn * 8];
    bv1.f = *(const float4*)&bias[n0 + tn * 8 + 4];
    u64 bias2[4] = {bv0.u.x, bv0.u.y, bv1.u.x, bv1.u.y};

    #pragma unroll
    for (int i = 0; i < 8; i++) {
        const int row = m0 + tm * 8 + i;
        float* dst = &g_xz[dir][row][n0 + tn * 8];
        double2 o0, o1;
        o0.x = ull_as_d(add2_(acc2[i][0], bias2[0]));
        o0.y = ull_as_d(add2_(acc2[i][1], bias2[1]));
        o1.x = ull_as_d(add2_(acc2[i][2], bias2[2]));
        o1.y = ull_as_d(add2_(acc2[i][3], bias2[3]));
        __stcs((double2*)&dst[0], o0);
        __stcs((double2*)&dst[4], o1);
    }
}

// ---------------------------------------------------------------------------
// Persistent BiLSTM recurrence: ONE kernel runs all 256 steps.
// grid = 128 blocks (all co-resident), 256 threads.
// Block bx: dir = bx>>6, j-tile = (bx&63)*16. Each step:
//   z[64 x 16j x 4g] = xz[t] + h_prev @ U  (FFMA2, double-buffered SMEM)
//   gates -> c (REGISTERS, block-exclusive) -> h -> g_h[wbuf] + out
//   grid_barrier before the next step reads the freshly written h buffer.
// h crosses SMs via ld.cg/st.cg (L2 = coherence point); U via normal cached
// loads (no per-launch L1 flush anymore -> U can stay L1/L2-hot all 256 steps).
// ---------------------------------------------------------------------------
__device__ __forceinline__ float sigmoidf_(float v) {
    return 1.0f / (1.0f + __expf(-v));
}

#define HSPAD 68   // row pad (words); multiple of 4 keeps 16B alignment

__global__ __launch_bounds__(256, 1)
void persistent_lstm_kernel(const float* __restrict__ Uf,
                            const float* __restrict__ Ub,
                            float* __restrict__ out)
{
    const int bx  = blockIdx.x;
    const int dir = bx >> 6;
    const int j0  = (bx & 63) * 16;
    const float* __restrict__ U = dir ? Ub : Uf;

    __shared__ float Hs[2][16][HSPAD];   // [buf][k][b]
    __shared__ float Us[2][16][HSPAD];   // [buf][k][jj*4 + gate]

    const int tid = threadIdx.x;
    const int tm = tid >> 4;       // 0..15 -> rows (b) tm*4..+3
    const int tn = tid & 15;       // j lane (jj)
    const int j  = j0 + tn;

    const int hb  = tid >> 2;          // 0..63
    const int hk4 = (tid & 3) * 4;     // 0,4,8,12
    const int ukk = tid >> 4;          // 0..15
    const int ulane = tid & 15;

    const float* __restrict__ ubase = U + (size_t)ukk * G4 + j0 + ulane;
    const float* __restrict__ hsrc0 = &g_h[0][dir][hb][hk4];
    const float* __restrict__ hsrc1 = &g_h[1][dir][hb][hk4];

    // ---- phase 0: zero the s=0 read buffer for this block's slice; c -> regs
    #pragma unroll
    for (int r = 0; r < 4; r++)
        __stcg(&g_h[0][dir][tm * 4 + r][j], 0.0f);
    float c_reg[4] = {0.0f, 0.0f, 0.0f, 0.0f};
    grid_barrier(NBLK);

    // ---- 256 timesteps
    for (int s = 0; s < TT; s++) {
        const int t    = dir ? (TT - 1 - s) : s;
        const int rb   = s & 1;
        const int wbuf = rb ^ 1;
        const float* __restrict__ hsrc = rb ? hsrc1 : hsrc0;

        // prefetch xz for the epilogue (read-once stream: evict-first)
        float xzv[4][4];
        #pragma unroll
        for (int r = 0; r < 4; r++) {
            const int b = tm * 4 + r;
            const float* xz = &g_xz[dir][(size_t)b * TT + t][j];
            xzv[r][0] = __ldcs(xz);
            xzv[r][1] = __ldcs(xz + HH);
            xzv[r][2] = __ldcs(xz + 2 * HH);
            xzv[r][3] = __ldcs(xz + 3 * HH);
        }

        u64 acc2[2][4];   // [row-pair][gate]
        #pragma unroll
        for (int r2 = 0; r2 < 2; r2++)
            #pragma unroll
            for (int q = 0; q < 4; q++) acc2[r2][q] = 0ull;

        // prefetch chunk 0 (h via .cg: L2-coherent across SMs)
        float4 rh = __ldcg((const float4*)hsrc);
        float4 ru = make_float4(ubase[0], ubase[HH], ubase[2 * HH], ubase[3 * HH]);

        const int NCHUNK = HH / 16;  // 64
        for (int c = 0; c < NCHUNK; c++) {
            const int buf = c & 1;
            Hs[buf][hk4 + 0][hb] = rh.x;
            Hs[buf][hk4 + 1][hb] = rh.y;
            Hs[buf][hk4 + 2][hb] = rh.z;
            Hs[buf][hk4 + 3][hb] = rh.w;
            *(float4*)&Us[buf][ukk][ulane * 4] = ru;
            __syncthreads();

            if (c + 1 < NCHUNK) {
                const int k0 = (c + 1) * 16;
                rh = __ldcg((const float4*)(hsrc + k0));
                const float* up = ubase + (size_t)k0 * G4;
                ru = make_float4(up[0], up[HH], up[2 * HH], up[3 * HH]);
            }

            #pragma unroll
            for (int k = 0; k < 16; k++) {
                ulonglong2 hp = *(const ulonglong2*)&Hs[buf][k][tm * 4];
                float4 u4 = *(const float4*)&Us[buf][k][tn * 4];
                u64 ui = pack2_(u4.x);
                u64 uf = pack2_(u4.y);
                u64 ug = pack2_(u4.z);
                u64 uo = pack2_(u4.w);
                acc2[0][0] = fma2_(hp.x, ui, acc2[0][0]);
                acc2[0][1] = fma2_(hp.x, uf, acc2[0][1]);
                acc2[0][2] = fma2_(hp.x, ug, acc2[0][2]);
                acc2[0][3] = fma2_(hp.x, uo, acc2[0][3]);
                acc2[1][0] = fma2_(hp.y, ui, acc2[1][0]);
                acc2[1][1] = fma2_(hp.y, uf, acc2[1][1]);
                acc2[1][2] = fma2_(hp.y, ug, acc2[1][2]);
                acc2[1][3] = fma2_(hp.y, uo, acc2[1][3]);
            }
            // single barrier per chunk: next store to buf^1 only happens after
            // the next __syncthreads, by which time its readers are done.
        }

        // unpack accumulators
        float accf[4][4];
        #pragma unroll
        for (int r2 = 0; r2 < 2; r2++)
            #pragma unroll
            for (int q = 0; q < 4; q++)
                unpack2_(acc2[r2][q], accf[2 * r2][q], accf[2 * r2 + 1][q]);

        #pragma unroll
        for (int r = 0; r < 4; r++) {
            const int b = tm * 4 + r;
            float zi = accf[r][0] + xzv[r][0];
            float zf = accf[r][1] + xzv[r][1];
            float zg = accf[r][2] + xzv[r][2];
            float zo = accf[r][3] + xzv[r][3];

            float gi = sigmoidf_(zi);
            float gf = sigmoidf_(zf);
            float gg = tanhf(zg);
            float go = sigmoidf_(zo);

            float cc = gf * c_reg[r] + gi * gg;
            c_reg[r] = cc;
            float h = go * tanhf(cc);

            __stcg(&g_h[wbuf][dir][b][j], h);
            __stcs(&out[(size_t)b * (TT * 2 * HH) + (size_t)t * (2 * HH) + dir * HH + j], h);
        }

        // all h[wbuf] writes must be visible before any block starts step s+1
        grid_barrier(NBLK * (unsigned)(s + 2));
    }
}

// ---------------------------------------------------------------------------
// Launch: reset barrier -> input GEMM -> ONE persistent recurrence kernel.
// ---------------------------------------------------------------------------
extern "C" void kernel_launch(void* const* d_in, const int* in_sizes, int n_in,
                              void* d_out, int out_size)
{
    const float* x  = (const float*)d_in[0];
    const float* Wf = (const float*)d_in[1];
    const float* Uf = (const float*)d_in[2];
    const float* bf = (const float*)d_in[3];
    const float* Wb = (const float*)d_in[4];
    const float* Ub = (const float*)d_in[5];
    const float* bb = (const float*)d_in[6];
    float* out = (float*)d_out;

    reset_kernel<<<1, 1>>>();

    dim3 ggrid(64, 128);
    input_gemm_kernel<<<ggrid, 256>>>(x, Wf, bf, Wb, bb);

    persistent_lstm_kernel<<<NBLK, 256>>>(Uf, Ub, out);
}